// round 7
// baseline (speedup 1.0000x reference)
#include <cuda_runtime.h>
#include <cstdint>

#define NROWS 4096
#define DIM   512
#define LAT   128
#define TOPK  16

#define BI 128
#define BJ 128
#define KC 16

// -------- scratch (static __device__ arrays; no runtime allocation) --------
__device__ float g_rec_test[NROWS * DIM];
__device__ float g_rec_train[NROWS * DIM];
__device__ float g_dist[(size_t)NROWS * NROWS];   // 64 MB, reused for both matrices
__device__ float g_pos[NROWS];
__device__ float g_neg[NROWS];

// -------- packed f32x2 helpers --------
__device__ __forceinline__ unsigned long long f2add(unsigned long long a, unsigned long long b) {
    unsigned long long r;
    asm("add.rn.f32x2 %0, %1, %2;" : "=l"(r) : "l"(a), "l"(b));
    return r;
}
__device__ __forceinline__ unsigned long long dup2(float x) {
    unsigned long long r;
    unsigned xi = __float_as_uint(x);
    asm("mov.b64 %0, {%1, %1};" : "=l"(r) : "r"(xi));
    return r;
}

// ---------------- GEMM: out[row,:] = lat[row,:] @ W + b ----------------
__global__ void gemm_kernel(const float* __restrict__ lat,
                            const float* __restrict__ W,
                            const float* __restrict__ b,
                            float* __restrict__ out) {
    __shared__ float s_lat[LAT];
    int row = blockIdx.x;
    int tx = threadIdx.x;                         // 0..127
    s_lat[tx] = lat[row * LAT + tx];
    __syncthreads();

    float4 acc = *(const float4*)&b[tx * 4];
    const float4* W4 = (const float4*)W;          // [LAT][DIM/4]
    #pragma unroll 8
    for (int l = 0; l < LAT; l++) {
        float a = s_lat[l];
        float4 w = W4[l * (DIM / 4) + tx];
        acc.x += a * w.x; acc.y += a * w.y; acc.z += a * w.z; acc.w += a * w.w;
    }
    *(float4*)&out[(size_t)row * DIM + tx * 4] = acc;
}

// ---------------- L1 cdist: Dout[i,j] = sum_d |X[i,d] - Y[j,d]| ----------------
// CTA tile 128x128, 256 threads (16x16), 8x8 register tile per thread,
// accumulators as packed f32x2. Single SMEM buffer, KC=16 (fastest measured).
// X tile stored PRE-DUPLICATED as (x,x) 64-bit pairs -> no per-k broadcast MOVs
// in the hot loop. Y tile stored NEGATED so diff = a + (-b). No register state
// held across the compute loop besides the accumulators (spill-safe).
__global__ __launch_bounds__(256, 2) void dist_kernel(
    const float* __restrict__ X, const float* __restrict__ Y,
    float* __restrict__ Dout)
{
    __shared__ __align__(16) unsigned long long Xd[KC][BI]; // 16 KB
    __shared__ __align__(16) float              Ys[KC][BJ]; //  8 KB

    int t  = threadIdx.x;
    int tx = t & 15;          // j-group
    int ty = t >> 4;          // i-group
    int i0 = blockIdx.y * BI;
    int j0 = blockIdx.x * BJ;

    unsigned long long acc[8][4];
    #pragma unroll
    for (int i = 0; i < 8; i++)
        #pragma unroll
        for (int jp = 0; jp < 4; jp++) acc[i][jp] = 0ULL;   // (0.0f, 0.0f)

    for (int k0 = 0; k0 < DIM; k0 += KC) {
        // ---- load tiles (transposed into [k][row]; X duplicated, Y negated) ----
        #pragma unroll
        for (int q = 0; q < 2; q++) {
            int s  = t + q * 256;          // 0..511
            int r  = s >> 2;               // tile row 0..127
            int kq = (s & 3) * 4;          // k-quad within chunk
            float4 xv = *(const float4*)&X[(size_t)(i0 + r) * DIM + k0 + kq];
            Xd[kq + 0][r] = dup2(xv.x);
            Xd[kq + 1][r] = dup2(xv.y);
            Xd[kq + 2][r] = dup2(xv.z);
            Xd[kq + 3][r] = dup2(xv.w);
            float4 yv = *(const float4*)&Y[(size_t)(j0 + r) * DIM + k0 + kq];
            Ys[kq + 0][r] = -yv.x;
            Ys[kq + 1][r] = -yv.y;
            Ys[kq + 2][r] = -yv.z;
            Ys[kq + 3][r] = -yv.w;
        }
        __syncthreads();

        #pragma unroll 4
        for (int k = 0; k < KC; k++) {
            ulonglong2 A0 = *(const ulonglong2*)&Xd[k][ty * 8];
            ulonglong2 A1 = *(const ulonglong2*)&Xd[k][ty * 8 + 2];
            ulonglong2 A2 = *(const ulonglong2*)&Xd[k][ty * 8 + 4];
            ulonglong2 A3 = *(const ulonglong2*)&Xd[k][ty * 8 + 6];
            ulonglong2 B0 = *(const ulonglong2*)&Ys[k][tx * 8];
            ulonglong2 B1 = *(const ulonglong2*)&Ys[k][tx * 8 + 4];
            unsigned long long aa[8] = { A0.x, A0.y, A1.x, A1.y, A2.x, A2.y, A3.x, A3.y };
            unsigned long long bb[4] = { B0.x, B0.y, B1.x, B1.y };
            #pragma unroll
            for (int i = 0; i < 8; i++) {
                #pragma unroll
                for (int jp = 0; jp < 4; jp++) {
                    unsigned long long d = f2add(aa[i], bb[jp]);   // (a-b0, a-b1)
                    d &= 0x7FFFFFFF7FFFFFFFULL;                    // packed abs (2x LOP3)
                    acc[i][jp] = f2add(acc[i][jp], d);
                }
            }
        }
        __syncthreads();
    }

    // ---- store 8x8 tile (32B-aligned packed stores) ----
    #pragma unroll
    for (int i = 0; i < 8; i++) {
        size_t base = (size_t)(i0 + ty * 8 + i) * NROWS + (j0 + tx * 8);
        ulonglong2 o0 = { acc[i][0], acc[i][1] };
        ulonglong2 o1 = { acc[i][2], acc[i][3] };
        *(ulonglong2*)&Dout[base]     = o0;
        *(ulonglong2*)&Dout[base + 4] = o1;
    }
}

// ---------------- per-row top-16 smallest distances -> mean of reciprocals ----------------
// one warp per row; register-resident branch-free sorted insert (static indices),
// float4 loads for MLP; 32-way shfl merge at the end.
__device__ __forceinline__ void topk_insert(float (&best)[TOPK], float v) {
    if (v < best[TOPK - 1]) {
        #pragma unroll
        for (int i = TOPK - 1; i > 0; i--)
            best[i] = fminf(fmaxf(v, best[i - 1]), best[i]);
        best[0] = fminf(best[0], v);
    }
}

__global__ void topk_kernel(const float* __restrict__ Dmat, float* __restrict__ out) {
    int warp_global = (blockIdx.x * blockDim.x + threadIdx.x) >> 5;
    int lane = threadIdx.x & 31;
    if (warp_global >= NROWS) return;
    const float4* row4 = (const float4*)(Dmat + (size_t)warp_global * NROWS);

    const float INF = __int_as_float(0x7f800000);
    float best[TOPK];
    #pragma unroll
    for (int i = 0; i < TOPK; i++) best[i] = INF;

    for (int c = lane; c < NROWS / 4; c += 32) {
        float4 v = row4[c];
        topk_insert(best, v.x);
        topk_insert(best, v.y);
        topk_insert(best, v.z);
        topk_insert(best, v.w);
    }

    // merge 32 sorted ascending lists, extract 16 global smallest
    int h = 0;
    float ssum = 0.f;
    #pragma unroll
    for (int r = 0; r < TOPK; r++) {
        float v = (h < TOPK) ? best[h] : INF;
        float m = v;
        #pragma unroll
        for (int off = 16; off; off >>= 1)
            m = fminf(m, __shfl_xor_sync(0xffffffffu, m, off));
        unsigned bal = __ballot_sync(0xffffffffu, v == m);
        if (lane == (__ffs(bal) - 1)) h++;
        ssum += 1.0f / m;
    }
    if (lane == 0) out[warp_global] = ssum * (1.0f / TOPK);
}

// ---------------- final: huber(relu(neg - pos)).mean() ----------------
__global__ void final_kernel(const float* __restrict__ pos,
                             const float* __restrict__ neg,
                             float* __restrict__ out) {
    __shared__ float sred[256];
    float s = 0.f;
    for (int i = threadIdx.x; i < NROWS; i += 256) {
        float l = neg[i] - pos[i];
        l = fmaxf(l, 0.f);
        float h = (l <= 1.0f) ? 0.5f * l * l : (l - 0.5f);
        s += h;
    }
    sred[threadIdx.x] = s;
    __syncthreads();
    for (int st = 128; st; st >>= 1) {
        if (threadIdx.x < st) sred[threadIdx.x] += sred[threadIdx.x + st];
        __syncthreads();
    }
    if (threadIdx.x == 0) out[0] = sred[0] * (1.0f / NROWS);
}

// ---------------- launch ----------------
extern "C" void kernel_launch(void* const* d_in, const int* in_sizes, int n_in,
                              void* d_out, int out_size) {
    const float* gt_vals      = (const float*)d_in[0];   // [4096, 512]
    const float* train_latent = (const float*)d_in[1];   // [4096, 128]
    const float* test_latent  = (const float*)d_in[2];   // [4096, 128]
    const float* W            = (const float*)d_in[3];   // [128, 512]
    const float* b            = (const float*)d_in[4];   // [512]
    float* out = (float*)d_out;

    float *rec_test, *rec_train, *dist, *pos, *neg;
    cudaGetSymbolAddress((void**)&rec_test,  g_rec_test);
    cudaGetSymbolAddress((void**)&rec_train, g_rec_train);
    cudaGetSymbolAddress((void**)&dist,      g_dist);
    cudaGetSymbolAddress((void**)&pos,       g_pos);
    cudaGetSymbolAddress((void**)&neg,       g_neg);

    // 1) decode both latents
    gemm_kernel<<<NROWS, 128>>>(test_latent,  W, b, rec_test);
    gemm_kernel<<<NROWS, 128>>>(train_latent, W, b, rec_train);

    dim3 dgrid(NROWS / BJ, NROWS / BI);

    // 2) positive: cdist(rec_test, gt_vals) -> top-k
    dist_kernel<<<dgrid, 256>>>(rec_test, gt_vals, dist);
    topk_kernel<<<(NROWS * 32) / 256, 256>>>(dist, pos);

    // 3) negative: cdist(rec_test, rec_train) -> top-k
    dist_kernel<<<dgrid, 256>>>(rec_test, rec_train, dist);
    topk_kernel<<<(NROWS * 32) / 256, 256>>>(dist, neg);

    // 4) huber mean
    final_kernel<<<1, 256>>>(pos, neg, out);
}

// round 8
// speedup vs baseline: 1.0873x; 1.0873x over previous
#include <cuda_runtime.h>
#include <cstdint>

#define NROWS 4096
#define DIM   512
#define LAT   128
#define TOPK  16

#define BI 128
#define BJ 128
#define KC 16
#define NCHUNK (DIM / KC)
#define PADW 132          // padded SMEM row width (floats): 2-way max STS conflict, 16B-aligned rows

// -------- scratch (static __device__ arrays; no runtime allocation) --------
__device__ float g_rec_test[NROWS * DIM];
__device__ float g_rec_train_neg[NROWS * DIM];   // decoded train latents, NEGATED
__device__ float g_gt_neg[NROWS * DIM];          // gt_vals, NEGATED
__device__ float g_dist[(size_t)NROWS * NROWS];  // 64 MB, reused for both matrices
__device__ float g_pos[NROWS];
__device__ float g_neg[NROWS];

// -------- packed f32x2 helpers --------
__device__ __forceinline__ unsigned long long f2add(unsigned long long a, unsigned long long b) {
    unsigned long long r;
    asm("add.rn.f32x2 %0, %1, %2;" : "=l"(r) : "l"(a), "l"(b));
    return r;
}
__device__ __forceinline__ unsigned long long dup2(float x) {
    unsigned long long r;
    unsigned xi = __float_as_uint(x);
    asm("mov.b64 %0, {%1, %1};" : "=l"(r) : "r"(xi));
    return r;
}

// -------- cp.async helpers --------
__device__ __forceinline__ void cpa4(void* dst, const void* src) {
    unsigned d = (unsigned)__cvta_generic_to_shared(dst);
    asm volatile("cp.async.ca.shared.global [%0], [%1], 4;" :: "r"(d), "l"(src));
}
__device__ __forceinline__ void cpa_commit() {
    asm volatile("cp.async.commit_group;");
}
__device__ __forceinline__ void cpa_wait1() {
    asm volatile("cp.async.wait_group 1;");
}
__device__ __forceinline__ void cpa_wait0() {
    asm volatile("cp.async.wait_group 0;");
}

// ---------------- GEMM: out[row,:] = sgn * (lat[row,:] @ W + b) ----------------
__global__ void gemm_kernel(const float* __restrict__ lat,
                            const float* __restrict__ W,
                            const float* __restrict__ b,
                            float* __restrict__ out,
                            float sgn) {
    __shared__ float s_lat[LAT];
    int row = blockIdx.x;
    int tx = threadIdx.x;                         // 0..127
    s_lat[tx] = lat[row * LAT + tx];
    __syncthreads();

    float4 acc = *(const float4*)&b[tx * 4];
    const float4* W4 = (const float4*)W;          // [LAT][DIM/4]
    #pragma unroll 8
    for (int l = 0; l < LAT; l++) {
        float a = s_lat[l];
        float4 w = W4[l * (DIM / 4) + tx];
        acc.x += a * w.x; acc.y += a * w.y; acc.z += a * w.z; acc.w += a * w.w;
    }
    acc.x *= sgn; acc.y *= sgn; acc.z *= sgn; acc.w *= sgn;
    *(float4*)&out[(size_t)row * DIM + tx * 4] = acc;
}

// ---------------- negate copy: out = -in ----------------
__global__ void neg_kernel(const float* __restrict__ in, float* __restrict__ out) {
    int i = blockIdx.x * blockDim.x + threadIdx.x;
    float4 v = *(const float4*)&in[i * 4];
    float4 o = { -v.x, -v.y, -v.z, -v.w };
    *(float4*)&out[i * 4] = o;
}

// ---------------- L1 cdist: Dout[i,j] = sum_d |X[i,d] + Yn[j,d]|  (Yn pre-negated) ----
// CTA tile 128x128, 256 threads (16x16), 8x8 register tile, packed f32x2 accumulators.
// Double-buffered tiles filled by 4-byte cp.async (transpose via scatter; no data
// registers held across the compute loop). Compute loop identical to the proven R4 form.
__global__ __launch_bounds__(256, 2) void dist_kernel(
    const float* __restrict__ X, const float* __restrict__ Yn,
    float* __restrict__ Dout)
{
    __shared__ __align__(16) float Xs[2][KC][PADW];
    __shared__ __align__(16) float Ys[2][KC][PADW];

    int t  = threadIdx.x;
    int tx = t & 15;          // j-group
    int ty = t >> 4;          // i-group
    int i0 = blockIdx.y * BI;
    int j0 = blockIdx.x * BJ;

    unsigned long long acc[8][4];
    #pragma unroll
    for (int i = 0; i < 8; i++)
        #pragma unroll
        for (int jp = 0; jp < 4; jp++) acc[i][jp] = 0ULL;

    // async tile loader for chunk c into buffer buf
    auto load_chunk = [&](int c, int buf) {
        int k0 = c * KC;
        #pragma unroll
        for (int q = 0; q < 8; q++) {
            int s  = t + q * 256;      // 0..2047
            int r  = s >> 4;           // tile row 0..127
            int kk = s & 15;           // k within chunk
            cpa4(&Xs[buf][kk][r], &X [(size_t)(i0 + r) * DIM + k0 + kk]);
            cpa4(&Ys[buf][kk][r], &Yn[(size_t)(j0 + r) * DIM + k0 + kk]);
        }
        cpa_commit();
    };

    // prologue: prefetch chunks 0 and 1
    load_chunk(0, 0);
    load_chunk(1, 1);

    for (int c = 0; c < NCHUNK; c++) {
        int cb = c & 1;
        if (c == NCHUNK - 1) cpa_wait0(); else cpa_wait1();   // chunk c's data landed
        __syncthreads();

        #pragma unroll 4
        for (int k = 0; k < KC; k++) {
            float4 a0 = *(const float4*)&Xs[cb][k][ty * 8];
            float4 a1 = *(const float4*)&Xs[cb][k][ty * 8 + 4];
            ulonglong2 bq0 = *(const ulonglong2*)&Ys[cb][k][tx * 8];
            ulonglong2 bq1 = *(const ulonglong2*)&Ys[cb][k][tx * 8 + 4];
            unsigned long long bb[4] = { bq0.x, bq0.y, bq1.x, bq1.y };
            float av[8] = { a0.x, a0.y, a0.z, a0.w, a1.x, a1.y, a1.z, a1.w };
            #pragma unroll
            for (int i = 0; i < 8; i++) {
                unsigned long long a2 = dup2(av[i]);
                #pragma unroll
                for (int jp = 0; jp < 4; jp++) {
                    unsigned long long d = f2add(a2, bb[jp]);   // (a-b) packed (Y pre-negated)
                    d &= 0x7FFFFFFF7FFFFFFFULL;                 // packed abs (2x LOP3, ALU pipe)
                    acc[i][jp] = f2add(acc[i][jp], d);
                }
            }
        }
        __syncthreads();                                        // done reading buffer cb

        if (c + 2 < NCHUNK) load_chunk(c + 2, cb);              // refill the buffer just drained
    }

    // ---- store 8x8 tile (32B-aligned packed stores) ----
    #pragma unroll
    for (int i = 0; i < 8; i++) {
        size_t base = (size_t)(i0 + ty * 8 + i) * NROWS + (j0 + tx * 8);
        ulonglong2 o0 = { acc[i][0], acc[i][1] };
        ulonglong2 o1 = { acc[i][2], acc[i][3] };
        *(ulonglong2*)&Dout[base]     = o0;
        *(ulonglong2*)&Dout[base + 4] = o1;
    }
}

// ---------------- per-row top-16 smallest distances -> mean of reciprocals ----------------
__device__ __forceinline__ void topk_insert(float (&best)[TOPK], float v) {
    if (v < best[TOPK - 1]) {
        #pragma unroll
        for (int i = TOPK - 1; i > 0; i--)
            best[i] = fminf(fmaxf(v, best[i - 1]), best[i]);
        best[0] = fminf(best[0], v);
    }
}

__global__ void topk_kernel(const float* __restrict__ Dmat, float* __restrict__ out) {
    int warp_global = (blockIdx.x * blockDim.x + threadIdx.x) >> 5;
    int lane = threadIdx.x & 31;
    if (warp_global >= NROWS) return;
    const float4* row4 = (const float4*)(Dmat + (size_t)warp_global * NROWS);

    const float INF = __int_as_float(0x7f800000);
    float best[TOPK];
    #pragma unroll
    for (int i = 0; i < TOPK; i++) best[i] = INF;

    for (int c = lane; c < NROWS / 4; c += 32) {
        float4 v = row4[c];
        topk_insert(best, v.x);
        topk_insert(best, v.y);
        topk_insert(best, v.z);
        topk_insert(best, v.w);
    }

    int h = 0;
    float ssum = 0.f;
    #pragma unroll
    for (int r = 0; r < TOPK; r++) {
        float v = (h < TOPK) ? best[h] : INF;
        float m = v;
        #pragma unroll
        for (int off = 16; off; off >>= 1)
            m = fminf(m, __shfl_xor_sync(0xffffffffu, m, off));
        unsigned bal = __ballot_sync(0xffffffffu, v == m);
        if (lane == (__ffs(bal) - 1)) h++;
        ssum += 1.0f / m;
    }
    if (lane == 0) out[warp_global] = ssum * (1.0f / TOPK);
}

// ---------------- final: huber(relu(neg - pos)).mean() ----------------
__global__ void final_kernel(const float* __restrict__ pos,
                             const float* __restrict__ neg,
                             float* __restrict__ out) {
    __shared__ float sred[256];
    float s = 0.f;
    for (int i = threadIdx.x; i < NROWS; i += 256) {
        float l = neg[i] - pos[i];
        l = fmaxf(l, 0.f);
        float h = (l <= 1.0f) ? 0.5f * l * l : (l - 0.5f);
        s += h;
    }
    sred[threadIdx.x] = s;
    __syncthreads();
    for (int st = 128; st; st >>= 1) {
        if (threadIdx.x < st) sred[threadIdx.x] += sred[threadIdx.x + st];
        __syncthreads();
    }
    if (threadIdx.x == 0) out[0] = sred[0] * (1.0f / NROWS);
}

// ---------------- launch ----------------
extern "C" void kernel_launch(void* const* d_in, const int* in_sizes, int n_in,
                              void* d_out, int out_size) {
    const float* gt_vals      = (const float*)d_in[0];   // [4096, 512]
    const float* train_latent = (const float*)d_in[1];   // [4096, 128]
    const float* test_latent  = (const float*)d_in[2];   // [4096, 128]
    const float* W            = (const float*)d_in[3];   // [128, 512]
    const float* b            = (const float*)d_in[4];   // [512]
    float* out = (float*)d_out;

    float *rec_test, *rec_train_neg, *gt_neg, *dist, *pos, *neg;
    cudaGetSymbolAddress((void**)&rec_test,      g_rec_test);
    cudaGetSymbolAddress((void**)&rec_train_neg, g_rec_train_neg);
    cudaGetSymbolAddress((void**)&gt_neg,        g_gt_neg);
    cudaGetSymbolAddress((void**)&dist,          g_dist);
    cudaGetSymbolAddress((void**)&pos,           g_pos);
    cudaGetSymbolAddress((void**)&neg,           g_neg);

    // 1) decode both latents (train negated for the sub-free dist formulation)
    gemm_kernel<<<NROWS, 128>>>(test_latent,  W, b, rec_test,      1.0f);
    gemm_kernel<<<NROWS, 128>>>(train_latent, W, b, rec_train_neg, -1.0f);
    neg_kernel<<<(NROWS * DIM / 4) / 256, 256>>>(gt_vals, gt_neg);

    dim3 dgrid(NROWS / BJ, NROWS / BI);

    // 2) positive: cdist(rec_test, gt_vals) -> top-k
    dist_kernel<<<dgrid, 256>>>(rec_test, gt_neg, dist);
    topk_kernel<<<(NROWS * 32) / 256, 256>>>(dist, pos);

    // 3) negative: cdist(rec_test, rec_train) -> top-k
    dist_kernel<<<dgrid, 256>>>(rec_test, rec_train_neg, dist);
    topk_kernel<<<(NROWS * 32) / 256, 256>>>(dist, neg);

    // 4) huber mean
    final_kernel<<<1, 256>>>(pos, neg, out);
}

// round 9
// speedup vs baseline: 1.1357x; 1.0445x over previous
#include <cuda_runtime.h>
#include <cstdint>

#define NROWS 4096
#define DIM   512
#define LAT   128
#define TOPK  16

#define BI 128
#define BJ 128
#define KC 16

// -------- scratch (static __device__ arrays; no runtime allocation) --------
__device__ float g_rec_test[NROWS * DIM];
__device__ float g_rec_train[NROWS * DIM];
__device__ float g_dist[(size_t)NROWS * NROWS];   // 64 MB, reused for both matrices
__device__ float g_pos[NROWS];
__device__ float g_neg[NROWS];

// -------- packed f32x2 helpers --------
__device__ __forceinline__ unsigned long long f2add(unsigned long long a, unsigned long long b) {
    unsigned long long r;
    asm("add.rn.f32x2 %0, %1, %2;" : "=l"(r) : "l"(a), "l"(b));
    return r;
}
__device__ __forceinline__ unsigned long long dup2(float x) {
    unsigned long long r;
    unsigned xi = __float_as_uint(x);
    asm("mov.b64 %0, {%1, %1};" : "=l"(r) : "r"(xi));
    return r;
}

// ---------------- GEMM: out[row,:] = lat[row,:] @ W + b ----------------
__global__ void gemm_kernel(const float* __restrict__ lat,
                            const float* __restrict__ W,
                            const float* __restrict__ b,
                            float* __restrict__ out) {
    __shared__ float s_lat[LAT];
    int row = blockIdx.x;
    int tx = threadIdx.x;                         // 0..127
    s_lat[tx] = lat[row * LAT + tx];
    __syncthreads();

    float4 acc = *(const float4*)&b[tx * 4];
    const float4* W4 = (const float4*)W;          // [LAT][DIM/4]
    #pragma unroll 8
    for (int l = 0; l < LAT; l++) {
        float a = s_lat[l];
        float4 w = W4[l * (DIM / 4) + tx];
        acc.x += a * w.x; acc.y += a * w.y; acc.z += a * w.z; acc.w += a * w.w;
    }
    *(float4*)&out[(size_t)row * DIM + tx * 4] = acc;
}

// ---------------- L1 cdist: Dout[i,j] = sum_d |X[i,d] - Y[j,d]| ----------------
// CTA tile 128x128, 512 threads (16x32), 4x8 register tile per thread.
// Half the per-thread accumulator state of the 8x8 version -> ~60 regs ->
// 2 CTAs x 512 threads = 32 warps/SM (2x the latency hiding at identical
// per-element pipe demand). Y tile negated on STS so diff = a + (-b);
// packed f32x2 accumulate, abs via 64-bit mask (2x LOP3 on the alu pipe).
__global__ __launch_bounds__(512, 2) void dist_kernel(
    const float* __restrict__ X, const float* __restrict__ Y,
    float* __restrict__ Dout)
{
    __shared__ float Xs[KC][BI];   // 8 KB
    __shared__ float Ys[KC][BJ];   // 8 KB

    int t  = threadIdx.x;
    int tx = t & 15;          // j-group: 16 groups x 8 cols
    int ty = t >> 4;          // i-group: 32 groups x 4 rows
    int i0 = blockIdx.y * BI;
    int j0 = blockIdx.x * BJ;

    unsigned long long acc[4][4];
    #pragma unroll
    for (int i = 0; i < 4; i++)
        #pragma unroll
        for (int jp = 0; jp < 4; jp++) acc[i][jp] = 0ULL;   // (0.0f, 0.0f)

    for (int k0 = 0; k0 < DIM; k0 += KC) {
        // ---- load tiles: exactly one float4 per thread per tile ----
        {
            int r  = t >> 2;               // tile row 0..127
            int kq = (t & 3) * 4;          // k-quad within chunk
            float4 xv = *(const float4*)&X[(size_t)(i0 + r) * DIM + k0 + kq];
            Xs[kq + 0][r] = xv.x; Xs[kq + 1][r] = xv.y;
            Xs[kq + 2][r] = xv.z; Xs[kq + 3][r] = xv.w;
            float4 yv = *(const float4*)&Y[(size_t)(j0 + r) * DIM + k0 + kq];
            Ys[kq + 0][r] = -yv.x; Ys[kq + 1][r] = -yv.y;
            Ys[kq + 2][r] = -yv.z; Ys[kq + 3][r] = -yv.w;
        }
        __syncthreads();

        #pragma unroll 4
        for (int k = 0; k < KC; k++) {
            float4 a0 = *(const float4*)&Xs[k][ty * 4];                    // broadcast LDS.128
            ulonglong2 bq0 = *(const ulonglong2*)&Ys[k][tx * 8];
            ulonglong2 bq1 = *(const ulonglong2*)&Ys[k][tx * 8 + 4];
            unsigned long long bb[4] = { bq0.x, bq0.y, bq1.x, bq1.y };
            float av[4] = { a0.x, a0.y, a0.z, a0.w };
            #pragma unroll
            for (int i = 0; i < 4; i++) {
                unsigned long long a2 = dup2(av[i]);
                #pragma unroll
                for (int jp = 0; jp < 4; jp++) {
                    unsigned long long d = f2add(a2, bb[jp]);   // (a-b) packed
                    d &= 0x7FFFFFFF7FFFFFFFULL;                 // packed abs (2x LOP3, alu pipe)
                    acc[i][jp] = f2add(acc[i][jp], d);
                }
            }
        }
        __syncthreads();
    }

    // ---- store 4x8 tile (32B-aligned packed stores) ----
    #pragma unroll
    for (int i = 0; i < 4; i++) {
        size_t base = (size_t)(i0 + ty * 4 + i) * NROWS + (j0 + tx * 8);
        ulonglong2 o0 = { acc[i][0], acc[i][1] };
        ulonglong2 o1 = { acc[i][2], acc[i][3] };
        *(ulonglong2*)&Dout[base]     = o0;
        *(ulonglong2*)&Dout[base + 4] = o1;
    }
}

// ---------------- per-row top-16 smallest distances -> mean of reciprocals ----------------
// one warp per row; register-resident branch-free sorted insert (static indices),
// float4 loads for MLP; 32-way shfl merge at the end.
__device__ __forceinline__ void topk_insert(float (&best)[TOPK], float v) {
    if (v < best[TOPK - 1]) {
        #pragma unroll
        for (int i = TOPK - 1; i > 0; i--)
            best[i] = fminf(fmaxf(v, best[i - 1]), best[i]);
        best[0] = fminf(best[0], v);
    }
}

__global__ void topk_kernel(const float* __restrict__ Dmat, float* __restrict__ out) {
    int warp_global = (blockIdx.x * blockDim.x + threadIdx.x) >> 5;
    int lane = threadIdx.x & 31;
    if (warp_global >= NROWS) return;
    const float4* row4 = (const float4*)(Dmat + (size_t)warp_global * NROWS);

    const float INF = __int_as_float(0x7f800000);
    float best[TOPK];
    #pragma unroll
    for (int i = 0; i < TOPK; i++) best[i] = INF;

    for (int c = lane; c < NROWS / 4; c += 32) {
        float4 v = row4[c];
        topk_insert(best, v.x);
        topk_insert(best, v.y);
        topk_insert(best, v.z);
        topk_insert(best, v.w);
    }

    // merge 32 sorted ascending lists, extract 16 global smallest
    int h = 0;
    float ssum = 0.f;
    #pragma unroll
    for (int r = 0; r < TOPK; r++) {
        float v = (h < TOPK) ? best[h] : INF;
        float m = v;
        #pragma unroll
        for (int off = 16; off; off >>= 1)
            m = fminf(m, __shfl_xor_sync(0xffffffffu, m, off));
        unsigned bal = __ballot_sync(0xffffffffu, v == m);
        if (lane == (__ffs(bal) - 1)) h++;
        ssum += 1.0f / m;
    }
    if (lane == 0) out[warp_global] = ssum * (1.0f / TOPK);
}

// ---------------- final: huber(relu(neg - pos)).mean() ----------------
__global__ void final_kernel(const float* __restrict__ pos,
                             const float* __restrict__ neg,
                             float* __restrict__ out) {
    __shared__ float sred[256];
    float s = 0.f;
    for (int i = threadIdx.x; i < NROWS; i += 256) {
        float l = neg[i] - pos[i];
        l = fmaxf(l, 0.f);
        float h = (l <= 1.0f) ? 0.5f * l * l : (l - 0.5f);
        s += h;
    }
    sred[threadIdx.x] = s;
    __syncthreads();
    for (int st = 128; st; st >>= 1) {
        if (threadIdx.x < st) sred[threadIdx.x] += sred[threadIdx.x + st];
        __syncthreads();
    }
    if (threadIdx.x == 0) out[0] = sred[0] * (1.0f / NROWS);
}

// ---------------- launch ----------------
extern "C" void kernel_launch(void* const* d_in, const int* in_sizes, int n_in,
                              void* d_out, int out_size) {
    const float* gt_vals      = (const float*)d_in[0];   // [4096, 512]
    const float* train_latent = (const float*)d_in[1];   // [4096, 128]
    const float* test_latent  = (const float*)d_in[2];   // [4096, 128]
    const float* W            = (const float*)d_in[3];   // [128, 512]
    const float* b            = (const float*)d_in[4];   // [512]
    float* out = (float*)d_out;

    float *rec_test, *rec_train, *dist, *pos, *neg;
    cudaGetSymbolAddress((void**)&rec_test,  g_rec_test);
    cudaGetSymbolAddress((void**)&rec_train, g_rec_train);
    cudaGetSymbolAddress((void**)&dist,      g_dist);
    cudaGetSymbolAddress((void**)&pos,       g_pos);
    cudaGetSymbolAddress((void**)&neg,       g_neg);

    // 1) decode both latents
    gemm_kernel<<<NROWS, 128>>>(test_latent,  W, b, rec_test);
    gemm_kernel<<<NROWS, 128>>>(train_latent, W, b, rec_train);

    dim3 dgrid(NROWS / BJ, NROWS / BI);

    // 2) positive: cdist(rec_test, gt_vals) -> top-k
    dist_kernel<<<dgrid, 512>>>(rec_test, gt_vals, dist);
    topk_kernel<<<(NROWS * 32) / 256, 256>>>(dist, pos);

    // 3) negative: cdist(rec_test, rec_train) -> top-k
    dist_kernel<<<dgrid, 512>>>(rec_test, rec_train, dist);
    topk_kernel<<<(NROWS * 32) / 256, 256>>>(dist, neg);

    // 4) huber mean
    final_kernel<<<1, 256>>>(pos, neg, out);
}

// round 10
// speedup vs baseline: 1.1632x; 1.0242x over previous
#include <cuda_runtime.h>
#include <cstdint>

#define NROWS 4096
#define DIM   512
#define LAT   128
#define TOPK  16

#define BI 128
#define BJ 128
#define KC 16

// -------- scratch (static __device__ arrays; no runtime allocation) --------
__device__ float g_rec_test[NROWS * DIM];
__device__ float g_rec_train[NROWS * DIM];
__device__ float g_dist[(size_t)NROWS * NROWS];   // 64 MB, reused for both matrices
__device__ float g_pos[NROWS];
__device__ float g_neg[NROWS];

// -------- packed f32x2 helpers --------
__device__ __forceinline__ unsigned long long f2add(unsigned long long a, unsigned long long b) {
    unsigned long long r;
    asm("add.rn.f32x2 %0, %1, %2;" : "=l"(r) : "l"(a), "l"(b));
    return r;
}
__device__ __forceinline__ unsigned long long dup2(float x) {
    unsigned long long r;
    unsigned xi = __float_as_uint(x);
    asm("mov.b64 %0, {%1, %1};" : "=l"(r) : "r"(xi));
    return r;
}

// ---------------- GEMM: out[row,:] = lat[row,:] @ W + b ----------------
__global__ void gemm_kernel(const float* __restrict__ lat,
                            const float* __restrict__ W,
                            const float* __restrict__ b,
                            float* __restrict__ out) {
    __shared__ float s_lat[LAT];
    int row = blockIdx.x;
    int tx = threadIdx.x;                         // 0..127
    s_lat[tx] = lat[row * LAT + tx];
    __syncthreads();

    float4 acc = *(const float4*)&b[tx * 4];
    const float4* W4 = (const float4*)W;          // [LAT][DIM/4]
    #pragma unroll 8
    for (int l = 0; l < LAT; l++) {
        float a = s_lat[l];
        float4 w = W4[l * (DIM / 4) + tx];
        acc.x += a * w.x; acc.y += a * w.y; acc.z += a * w.z; acc.w += a * w.w;
    }
    *(float4*)&out[(size_t)row * DIM + tx * 4] = acc;
}

// ---------------- L1 cdist: Dout[i,j] = sum_d |X[i,d] - Y[j,d]| ----------------
// CTA tile 128x128, 512 threads (16x32), 4x8 register tile per thread.
// j-fragment is SPLIT: two 4-column chunks at tx*4 and 64+tx*4 so the Ys
// LDS.128 phase banks are (tx*4 mod 32) = all distinct -> conflict-free
// (the old tx*8 layout was 2-way conflicted, making the smem crossbar the
// binding pipe at 640 cyc/SM/k vs 512 fma cyc). Y negated on STS so
// diff = a + (-b); packed f32x2 accumulate, abs via 64-bit mask (LOP3/alu).
__global__ __launch_bounds__(512, 2) void dist_kernel(
    const float* __restrict__ X, const float* __restrict__ Y,
    float* __restrict__ Dout)
{
    __shared__ float Xs[KC][BI];   // 8 KB
    __shared__ float Ys[KC][BJ];   // 8 KB

    int t  = threadIdx.x;
    int tx = t & 15;          // j-group: chunks at tx*4 and 64+tx*4
    int ty = t >> 4;          // i-group: 32 groups x 4 rows
    int i0 = blockIdx.y * BI;
    int j0 = blockIdx.x * BJ;

    unsigned long long acc[4][4];
    #pragma unroll
    for (int i = 0; i < 4; i++)
        #pragma unroll
        for (int jp = 0; jp < 4; jp++) acc[i][jp] = 0ULL;   // (0.0f, 0.0f)

    for (int k0 = 0; k0 < DIM; k0 += KC) {
        // ---- load tiles: exactly one float4 per thread per tile ----
        {
            int r  = t >> 2;               // tile row 0..127
            int kq = (t & 3) * 4;          // k-quad within chunk
            float4 xv = *(const float4*)&X[(size_t)(i0 + r) * DIM + k0 + kq];
            Xs[kq + 0][r] = xv.x; Xs[kq + 1][r] = xv.y;
            Xs[kq + 2][r] = xv.z; Xs[kq + 3][r] = xv.w;
            float4 yv = *(const float4*)&Y[(size_t)(j0 + r) * DIM + k0 + kq];
            Ys[kq + 0][r] = -yv.x; Ys[kq + 1][r] = -yv.y;
            Ys[kq + 2][r] = -yv.z; Ys[kq + 3][r] = -yv.w;
        }
        __syncthreads();

        #pragma unroll 4
        for (int k = 0; k < KC; k++) {
            float4 a0 = *(const float4*)&Xs[k][ty * 4];                 // broadcast LDS.128
            ulonglong2 bq0 = *(const ulonglong2*)&Ys[k][tx * 4];        // conflict-free
            ulonglong2 bq1 = *(const ulonglong2*)&Ys[k][64 + tx * 4];   // conflict-free
            unsigned long long bb[4] = { bq0.x, bq0.y, bq1.x, bq1.y };
            float av[4] = { a0.x, a0.y, a0.z, a0.w };
            #pragma unroll
            for (int i = 0; i < 4; i++) {
                unsigned long long a2 = dup2(av[i]);
                #pragma unroll
                for (int jp = 0; jp < 4; jp++) {
                    unsigned long long d = f2add(a2, bb[jp]);   // (a-b) packed
                    d &= 0x7FFFFFFF7FFFFFFFULL;                 // packed abs (2x LOP3, alu pipe)
                    acc[i][jp] = f2add(acc[i][jp], d);
                }
            }
        }
        __syncthreads();
    }

    // ---- store 4x8 tile: two 16B chunks per row at j = tx*4 and 64+tx*4 ----
    #pragma unroll
    for (int i = 0; i < 4; i++) {
        size_t rowb = (size_t)(i0 + ty * 4 + i) * NROWS + j0;
        ulonglong2 o0 = { acc[i][0], acc[i][1] };
        ulonglong2 o1 = { acc[i][2], acc[i][3] };
        *(ulonglong2*)&Dout[rowb + tx * 4]      = o0;
        *(ulonglong2*)&Dout[rowb + 64 + tx * 4] = o1;
    }
}

// ---------------- per-row top-16 smallest distances -> mean of reciprocals ----------------
// one warp per row; register-resident branch-free sorted insert (static indices),
// float4 loads for MLP; 32-way shfl merge at the end.
__device__ __forceinline__ void topk_insert(float (&best)[TOPK], float v) {
    if (v < best[TOPK - 1]) {
        #pragma unroll
        for (int i = TOPK - 1; i > 0; i--)
            best[i] = fminf(fmaxf(v, best[i - 1]), best[i]);
        best[0] = fminf(best[0], v);
    }
}

__global__ void topk_kernel(const float* __restrict__ Dmat, float* __restrict__ out) {
    int warp_global = (blockIdx.x * blockDim.x + threadIdx.x) >> 5;
    int lane = threadIdx.x & 31;
    if (warp_global >= NROWS) return;
    const float4* row4 = (const float4*)(Dmat + (size_t)warp_global * NROWS);

    const float INF = __int_as_float(0x7f800000);
    float best[TOPK];
    #pragma unroll
    for (int i = 0; i < TOPK; i++) best[i] = INF;

    for (int c = lane; c < NROWS / 4; c += 32) {
        float4 v = row4[c];
        topk_insert(best, v.x);
        topk_insert(best, v.y);
        topk_insert(best, v.z);
        topk_insert(best, v.w);
    }

    // merge 32 sorted ascending lists, extract 16 global smallest
    int h = 0;
    float ssum = 0.f;
    #pragma unroll
    for (int r = 0; r < TOPK; r++) {
        float v = (h < TOPK) ? best[h] : INF;
        float m = v;
        #pragma unroll
        for (int off = 16; off; off >>= 1)
            m = fminf(m, __shfl_xor_sync(0xffffffffu, m, off));
        unsigned bal = __ballot_sync(0xffffffffu, v == m);
        if (lane == (__ffs(bal) - 1)) h++;
        ssum += 1.0f / m;
    }
    if (lane == 0) out[warp_global] = ssum * (1.0f / TOPK);
}

// ---------------- final: huber(relu(neg - pos)).mean() ----------------
__global__ void final_kernel(const float* __restrict__ pos,
                             const float* __restrict__ neg,
                             float* __restrict__ out) {
    __shared__ float sred[256];
    float s = 0.f;
    for (int i = threadIdx.x; i < NROWS; i += 256) {
        float l = neg[i] - pos[i];
        l = fmaxf(l, 0.f);
        float h = (l <= 1.0f) ? 0.5f * l * l : (l - 0.5f);
        s += h;
    }
    sred[threadIdx.x] = s;
    __syncthreads();
    for (int st = 128; st; st >>= 1) {
        if (threadIdx.x < st) sred[threadIdx.x] += sred[threadIdx.x + st];
        __syncthreads();
    }
    if (threadIdx.x == 0) out[0] = sred[0] * (1.0f / NROWS);
}

// ---------------- launch ----------------
extern "C" void kernel_launch(void* const* d_in, const int* in_sizes, int n_in,
                              void* d_out, int out_size) {
    const float* gt_vals      = (const float*)d_in[0];   // [4096, 512]
    const float* train_latent = (const float*)d_in[1];   // [4096, 128]
    const float* test_latent  = (const float*)d_in[2];   // [4096, 128]
    const float* W            = (const float*)d_in[3];   // [128, 512]
    const float* b            = (const float*)d_in[4];   // [512]
    float* out = (float*)d_out;

    float *rec_test, *rec_train, *dist, *pos, *neg;
    cudaGetSymbolAddress((void**)&rec_test,  g_rec_test);
    cudaGetSymbolAddress((void**)&rec_train, g_rec_train);
    cudaGetSymbolAddress((void**)&dist,      g_dist);
    cudaGetSymbolAddress((void**)&pos,       g_pos);
    cudaGetSymbolAddress((void**)&neg,       g_neg);

    // 1) decode both latents
    gemm_kernel<<<NROWS, 128>>>(test_latent,  W, b, rec_test);
    gemm_kernel<<<NROWS, 128>>>(train_latent, W, b, rec_train);

    dim3 dgrid(NROWS / BJ, NROWS / BI);

    // 2) positive: cdist(rec_test, gt_vals) -> top-k
    dist_kernel<<<dgrid, 512>>>(rec_test, gt_vals, dist);
    topk_kernel<<<(NROWS * 32) / 256, 256>>>(dist, pos);

    // 3) negative: cdist(rec_test, rec_train) -> top-k
    dist_kernel<<<dgrid, 512>>>(rec_test, rec_train, dist);
    topk_kernel<<<(NROWS * 32) / 256, 256>>>(dist, neg);

    // 4) huber mean
    final_kernel<<<1, 256>>>(pos, neg, out);
}

// round 11
// speedup vs baseline: 1.2551x; 1.0790x over previous
#include <cuda_runtime.h>
#include <cstdint>

#define NROWS 4096
#define DIM   512
#define LAT   128
#define TOPK  16

#define BI 128
#define BJ 128
#define KC 16

// -------- scratch (static __device__ arrays; no runtime allocation) --------
__device__ float g_rec_test[NROWS * DIM];
__device__ float g_rec_train[NROWS * DIM];
__device__ float g_dist[(size_t)NROWS * NROWS];   // 64 MB, reused for both matrices
__device__ float g_pos[NROWS];
__device__ float g_neg[NROWS];

// -------- packed f32x2 helpers --------
__device__ __forceinline__ unsigned long long f2add(unsigned long long a, unsigned long long b) {
    unsigned long long r;
    asm("add.rn.f32x2 %0, %1, %2;" : "=l"(r) : "l"(a), "l"(b));
    return r;
}
__device__ __forceinline__ unsigned long long dup2(float x) {
    unsigned long long r;
    unsigned xi = __float_as_uint(x);
    asm("mov.b64 %0, {%1, %1};" : "=l"(r) : "r"(xi));
    return r;
}

// ---------------- GEMM: out[row,:] = lat[row,:] @ W + b ----------------
__global__ void gemm_kernel(const float* __restrict__ lat,
                            const float* __restrict__ W,
                            const float* __restrict__ b,
                            float* __restrict__ out) {
    __shared__ float s_lat[LAT];
    int row = blockIdx.x;
    int tx = threadIdx.x;                         // 0..127
    s_lat[tx] = lat[row * LAT + tx];
    __syncthreads();

    float4 acc = *(const float4*)&b[tx * 4];
    const float4* W4 = (const float4*)W;          // [LAT][DIM/4]
    #pragma unroll 8
    for (int l = 0; l < LAT; l++) {
        float a = s_lat[l];
        float4 w = W4[l * (DIM / 4) + tx];
        acc.x += a * w.x; acc.y += a * w.y; acc.z += a * w.z; acc.w += a * w.w;
    }
    *(float4*)&out[(size_t)row * DIM + tx * 4] = acc;
}

// ---------------- L1 cdist: Dout[i,j] = sum_d |X[i,d] - Y[j,d]| ----------------
// CTA tile 128x128, 512 threads (16x32), 4x8 register tile per thread.
// k-group XOR swizzle (row ^ ((k>>2)<<3)) makes BOTH the transposed STS scatter
// and all compute-side LDS.128 reads bank-conflict-free (the un-swizzled STS was
// 4-way conflicted: bank depended only on r, which spans just 8 values per warp).
// The XOR term is uniform per k and 8-aligned, so 4-aligned float4 groups stay
// contiguous -> reads remain single LDS.128s. Y negated on STS so diff = a+(-b);
// packed f32x2 accumulate, abs via 64-bit mask (2x LOP3, alu pipe).
__global__ __launch_bounds__(512, 2) void dist_kernel(
    const float* __restrict__ X, const float* __restrict__ Y,
    float* __restrict__ Dout)
{
    __shared__ float Xs[KC][BI];   // 8 KB
    __shared__ float Ys[KC][BJ];   // 8 KB

    int t  = threadIdx.x;
    int tx = t & 15;          // j-group: chunks at tx*4 and 64+tx*4 (swizzled)
    int ty = t >> 4;          // i-group: 32 groups x 4 rows
    int i0 = blockIdx.y * BI;
    int j0 = blockIdx.x * BJ;

    unsigned long long acc[4][4];
    #pragma unroll
    for (int i = 0; i < 4; i++)
        #pragma unroll
        for (int jp = 0; jp < 4; jp++) acc[i][jp] = 0ULL;   // (0.0f, 0.0f)

    for (int k0 = 0; k0 < DIM; k0 += KC) {
        // ---- load tiles (transposed + swizzled; conflict-free STS) ----
        {
            int r   = t >> 2;                    // tile row 0..127
            int kq  = (t & 3) * 4;               // k-quad within chunk
            int rsw = r ^ ((t & 3) << 3);        // row ^ ((k>>2)<<3), k>>2 == t&3 here
            float4 xv = *(const float4*)&X[(size_t)(i0 + r) * DIM + k0 + kq];
            Xs[kq + 0][rsw] = xv.x; Xs[kq + 1][rsw] = xv.y;
            Xs[kq + 2][rsw] = xv.z; Xs[kq + 3][rsw] = xv.w;
            float4 yv = *(const float4*)&Y[(size_t)(j0 + r) * DIM + k0 + kq];
            Ys[kq + 0][rsw] = -yv.x; Ys[kq + 1][rsw] = -yv.y;
            Ys[kq + 2][rsw] = -yv.z; Ys[kq + 3][rsw] = -yv.w;
        }
        __syncthreads();

        #pragma unroll
        for (int k = 0; k < KC; k++) {
            int grp = (k >> 2) << 3;             // compile-time per unrolled iter
            float4 a0 = *(const float4*)&Xs[k][(ty * 4) ^ grp];            // broadcast
            ulonglong2 bq0 = *(const ulonglong2*)&Ys[k][(tx * 4) ^ grp];   // conflict-free
            ulonglong2 bq1 = *(const ulonglong2*)&Ys[k][64 + ((tx * 4) ^ grp)];
            unsigned long long bb[4] = { bq0.x, bq0.y, bq1.x, bq1.y };
            float av[4] = { a0.x, a0.y, a0.z, a0.w };
            #pragma unroll
            for (int i = 0; i < 4; i++) {
                unsigned long long a2 = dup2(av[i]);
                #pragma unroll
                for (int jp = 0; jp < 4; jp++) {
                    unsigned long long d = f2add(a2, bb[jp]);   // (a-b) packed
                    d &= 0x7FFFFFFF7FFFFFFFULL;                 // packed abs (2x LOP3, alu)
                    acc[i][jp] = f2add(acc[i][jp], d);
                }
            }
        }
        __syncthreads();
    }

    // ---- store 4x8 tile: two 16B chunks per row at j = tx*4 and 64+tx*4 ----
    #pragma unroll
    for (int i = 0; i < 4; i++) {
        size_t rowb = (size_t)(i0 + ty * 4 + i) * NROWS + j0;
        ulonglong2 o0 = { acc[i][0], acc[i][1] };
        ulonglong2 o1 = { acc[i][2], acc[i][3] };
        *(ulonglong2*)&Dout[rowb + tx * 4]      = o0;
        *(ulonglong2*)&Dout[rowb + 64 + tx * 4] = o1;
    }
}

// ---------------- per-row top-16 smallest distances -> mean of reciprocals ----------------
// one warp per row; register-resident branch-free sorted insert (static indices),
// 2x float4 per iteration for MLP=2; 32-way shfl merge at the end.
__device__ __forceinline__ void topk_insert(float (&best)[TOPK], float v) {
    if (v < best[TOPK - 1]) {
        #pragma unroll
        for (int i = TOPK - 1; i > 0; i--)
            best[i] = fminf(fmaxf(v, best[i - 1]), best[i]);
        best[0] = fminf(best[0], v);
    }
}

__global__ void topk_kernel(const float* __restrict__ Dmat, float* __restrict__ out) {
    int warp_global = (blockIdx.x * blockDim.x + threadIdx.x) >> 5;
    int lane = threadIdx.x & 31;
    if (warp_global >= NROWS) return;
    const float4* row4 = (const float4*)(Dmat + (size_t)warp_global * NROWS);

    const float INF = __int_as_float(0x7f800000);
    float best[TOPK];
    #pragma unroll
    for (int i = 0; i < TOPK; i++) best[i] = INF;

    for (int c = lane; c < NROWS / 4; c += 64) {
        float4 v0 = row4[c];
        float4 v1 = row4[c + 32];
        topk_insert(best, v0.x);
        topk_insert(best, v0.y);
        topk_insert(best, v0.z);
        topk_insert(best, v0.w);
        topk_insert(best, v1.x);
        topk_insert(best, v1.y);
        topk_insert(best, v1.z);
        topk_insert(best, v1.w);
    }

    // merge 32 sorted ascending lists, extract 16 global smallest
    int h = 0;
    float ssum = 0.f;
    #pragma unroll
    for (int r = 0; r < TOPK; r++) {
        float v = (h < TOPK) ? best[h] : INF;
        float m = v;
        #pragma unroll
        for (int off = 16; off; off >>= 1)
            m = fminf(m, __shfl_xor_sync(0xffffffffu, m, off));
        unsigned bal = __ballot_sync(0xffffffffu, v == m);
        if (lane == (__ffs(bal) - 1)) h++;
        ssum += 1.0f / m;
    }
    if (lane == 0) out[warp_global] = ssum * (1.0f / TOPK);
}

// ---------------- final: huber(relu(neg - pos)).mean() ----------------
__global__ void final_kernel(const float* __restrict__ pos,
                             const float* __restrict__ neg,
                             float* __restrict__ out) {
    __shared__ float sred[256];
    float s = 0.f;
    for (int i = threadIdx.x; i < NROWS; i += 256) {
        float l = neg[i] - pos[i];
        l = fmaxf(l, 0.f);
        float h = (l <= 1.0f) ? 0.5f * l * l : (l - 0.5f);
        s += h;
    }
    sred[threadIdx.x] = s;
    __syncthreads();
    for (int st = 128; st; st >>= 1) {
        if (threadIdx.x < st) sred[threadIdx.x] += sred[threadIdx.x + st];
        __syncthreads();
    }
    if (threadIdx.x == 0) out[0] = sred[0] * (1.0f / NROWS);
}

// ---------------- launch ----------------
extern "C" void kernel_launch(void* const* d_in, const int* in_sizes, int n_in,
                              void* d_out, int out_size) {
    const float* gt_vals      = (const float*)d_in[0];   // [4096, 512]
    const float* train_latent = (const float*)d_in[1];   // [4096, 128]
    const float* test_latent  = (const float*)d_in[2];   // [4096, 128]
    const float* W            = (const float*)d_in[3];   // [128, 512]
    const float* b            = (const float*)d_in[4];   // [512]
    float* out = (float*)d_out;

    float *rec_test, *rec_train, *dist, *pos, *neg;
    cudaGetSymbolAddress((void**)&rec_test,  g_rec_test);
    cudaGetSymbolAddress((void**)&rec_train, g_rec_train);
    cudaGetSymbolAddress((void**)&dist,      g_dist);
    cudaGetSymbolAddress((void**)&pos,       g_pos);
    cudaGetSymbolAddress((void**)&neg,       g_neg);

    // 1) decode both latents
    gemm_kernel<<<NROWS, 128>>>(test_latent,  W, b, rec_test);
    gemm_kernel<<<NROWS, 128>>>(train_latent, W, b, rec_train);

    dim3 dgrid(NROWS / BJ, NROWS / BI);

    // 2) positive: cdist(rec_test, gt_vals) -> top-k
    dist_kernel<<<dgrid, 512>>>(rec_test, gt_vals, dist);
    topk_kernel<<<(NROWS * 32) / 256, 256>>>(dist, pos);

    // 3) negative: cdist(rec_test, rec_train) -> top-k
    dist_kernel<<<dgrid, 512>>>(rec_test, rec_train, dist);
    topk_kernel<<<(NROWS * 32) / 256, 256>>>(dist, neg);

    // 4) huber mean
    final_kernel<<<1, 256>>>(pos, neg, out);
}